// round 6
// baseline (speedup 1.0000x reference)
#include <cuda_runtime.h>
#include <cuda_bf16.h>
#include <cuda_fp16.h>
#include <cstdint>
#include <cstddef>

// Problem dims
#define Bv  4
#define Qv  1024
#define Kv  1024
#define Dv  256
#define Hv  64
#define DVv 256

// Scratch (allocation-free rule: __device__ globals)
__device__ __align__(16) __half g_qp[Bv * Qv * Hv];                   // 512 KB (f16)
__device__ __align__(16) __half g_kp[Bv * Kv * Hv];                   // 512 KB
__device__ __align__(16) __nv_bfloat16 g_ahi[(size_t)Bv * Qv * Kv];   // 8 MB
__device__ __align__(16) __nv_bfloat16 g_alo[(size_t)Bv * Qv * Kv];   // 8 MB
__device__ __align__(16) __nv_bfloat16 g_vhi[Bv * Kv * DVv];          // 2 MB
__device__ __align__(16) __nv_bfloat16 g_vlo[Bv * Kv * DVv];          // 2 MB

__device__ __forceinline__ uint32_t tanh2(uint32_t x) {
    uint32_t y;
    asm("tanh.approx.f16x2 %0, %1;" : "=r"(y) : "r"(x));
    return y;
}

__device__ __forceinline__ uint32_t s2u(const void* p) {
    uint32_t a;
    asm("{ .reg .u64 t; cvta.to.shared.u64 t, %1; cvt.u32.u64 %0, t; }" : "=r"(a) : "l"(p));
    return a;
}

__device__ __forceinline__ void cp16(uint32_t dst, const void* src) {
    asm volatile("cp.async.cg.shared.global [%0], [%1], 16;" :: "r"(dst), "l"(src));
}
__device__ __forceinline__ void cp_commit() { asm volatile("cp.async.commit_group;"); }
template <int N> __device__ __forceinline__ void cp_wait() {
    asm volatile("cp.async.wait_group %0;" :: "n"(N));
}

__device__ __forceinline__ void ldsm4(uint32_t* r, uint32_t addr) {
    asm volatile("ldmatrix.sync.aligned.m8n8.x4.shared.b16 {%0,%1,%2,%3}, [%4];"
                 : "=r"(r[0]), "=r"(r[1]), "=r"(r[2]), "=r"(r[3]) : "r"(addr));
}
__device__ __forceinline__ void ldsm4t(uint32_t* r, uint32_t addr) {
    asm volatile("ldmatrix.sync.aligned.m8n8.x4.trans.shared.b16 {%0,%1,%2,%3}, [%4];"
                 : "=r"(r[0]), "=r"(r[1]), "=r"(r[2]), "=r"(r[3]) : "r"(addr));
}
__device__ __forceinline__ void mma_bf16(float* d, const uint32_t* a, const uint32_t* b) {
    asm volatile(
        "mma.sync.aligned.m16n8k16.row.col.f32.bf16.bf16.f32 "
        "{%0,%1,%2,%3},{%4,%5,%6,%7},{%8,%9},{%0,%1,%2,%3};"
        : "+f"(d[0]), "+f"(d[1]), "+f"(d[2]), "+f"(d[3])
        : "r"(a[0]), "r"(a[1]), "r"(a[2]), "r"(a[3]), "r"(b[0]), "r"(b[1]));
}

// ---------------------------------------------------------------------------
// Fused: projections (f16 output) + values bf16 hi/lo split, one launch.
// ---------------------------------------------------------------------------
__global__ __launch_bounds__(256)
void proj_vsplit_kernel(const float* __restrict__ Qg, const float* __restrict__ Kg,
                        const float* __restrict__ Wq, const float* __restrict__ Wk,
                        const float* __restrict__ Vg)
{
    if (blockIdx.y >= 128) {
        const int blk = blockIdx.y - 128;          // 0..127
#pragma unroll
        for (int it = 0; it < 8; it++) {
            size_t idx4 = (size_t)blk * 256 + threadIdx.x + (size_t)it * 32768;
            size_t i = idx4 * 4;
            float4 v = *(const float4*)(Vg + i);
            __nv_bfloat16 h0 = __float2bfloat16(v.x), h1 = __float2bfloat16(v.y);
            __nv_bfloat16 h2 = __float2bfloat16(v.z), h3 = __float2bfloat16(v.w);
            __nv_bfloat16 l0 = __float2bfloat16(v.x - __bfloat162float(h0));
            __nv_bfloat16 l1 = __float2bfloat16(v.y - __bfloat162float(h1));
            __nv_bfloat16 l2 = __float2bfloat16(v.z - __bfloat162float(h2));
            __nv_bfloat16 l3 = __float2bfloat16(v.w - __bfloat162float(h3));
            *(ushort4*)(g_vhi + i) = make_ushort4(*(uint16_t*)&h0, *(uint16_t*)&h1, *(uint16_t*)&h2, *(uint16_t*)&h3);
            *(ushort4*)(g_vlo + i) = make_ushort4(*(uint16_t*)&l0, *(uint16_t*)&l1, *(uint16_t*)&l2, *(uint16_t*)&l3);
        }
        return;
    }

    const bool isQ = blockIdx.y < 64;
    const float* A = (isQ ? Qg : Kg) + (size_t)(blockIdx.y & 63) * 64 * 256;
    const float* B = isQ ? Wq : Wk;
    __half*      C = (isQ ? g_qp : g_kp) + (size_t)(blockIdx.y & 63) * 64 * 64;

    __shared__ float As[64][16];
    __shared__ float Bs[16][64];

    const int t    = threadIdx.x;
    const int trow = t >> 4;
    const int tcol = t & 15;
    const int a_row = t >> 2;
    const int a_k4  = (t & 3) << 2;
    const int b_k   = t >> 4;
    const int b_n4  = (t & 15) << 2;

    float acc[4][4] = {};

    for (int k0 = 0; k0 < 256; k0 += 16) {
        float4 av = *(const float4*)(A + (size_t)a_row * 256 + k0 + a_k4);
        float4 bv = *(const float4*)(B + (size_t)(k0 + b_k) * 64 + b_n4);
        *(float4*)&As[a_row][a_k4] = av;
        *(float4*)&Bs[b_k][b_n4]   = bv;
        __syncthreads();
#pragma unroll
        for (int kk = 0; kk < 16; kk++) {
            float4 b4 = *(const float4*)&Bs[kk][tcol << 2];
            float a0 = As[(trow << 2) + 0][kk];
            float a1 = As[(trow << 2) + 1][kk];
            float a2 = As[(trow << 2) + 2][kk];
            float a3 = As[(trow << 2) + 3][kk];
            acc[0][0] += a0 * b4.x; acc[0][1] += a0 * b4.y; acc[0][2] += a0 * b4.z; acc[0][3] += a0 * b4.w;
            acc[1][0] += a1 * b4.x; acc[1][1] += a1 * b4.y; acc[1][2] += a1 * b4.z; acc[1][3] += a1 * b4.w;
            acc[2][0] += a2 * b4.x; acc[2][1] += a2 * b4.y; acc[2][2] += a2 * b4.z; acc[2][3] += a2 * b4.w;
            acc[3][0] += a3 * b4.x; acc[3][1] += a3 * b4.y; acc[3][2] += a3 * b4.z; acc[3][3] += a3 * b4.w;
        }
        __syncthreads();
    }
#pragma unroll
    for (int i = 0; i < 4; i++) {
        __half2 h01 = __floats2half2_rn(acc[i][0], acc[i][1]);
        __half2 h23 = __floats2half2_rn(acc[i][2], acc[i][3]);
        uint2 pk = make_uint2(*(uint32_t*)&h01, *(uint32_t*)&h23);
        *(uint2*)(C + (size_t)((trow << 2) + i) * 64 + (tcol << 2)) = pk;
    }
}

// ---------------------------------------------------------------------------
// Fused scores + softmax: one CTA owns 32 q-rows x ALL K=1024.
// Scores live in 128KB smem; kp streamed in 64-k chunks (register dbl-buf);
// in-CTA softmax emits bf16 hi/lo attn planes directly.
// grid (32, 4), 256 threads, 152320 B dynamic smem.
// ---------------------------------------------------------------------------
#define SC_BYTES   (32 * 1024 * 4)          // 131072
#define QP_OFF     SC_BYTES
#define QP_BYTES   (32 * 33 * 4)            // 4224
#define KP_OFF     (QP_OFF + QP_BYTES)
#define KP_BYTES   (2 * 64 * 33 * 4)        // 16896
#define WV_OFF     (KP_OFF + KP_BYTES)
#define SMEM_SC_TOTAL (WV_OFF + 128)        // 152320

__global__ __launch_bounds__(256)
void scores_softmax_kernel(const float* __restrict__ wv_g)
{
    extern __shared__ char sm[];
    float   (*s_sc)[1024]   = (float(*)[1024])sm;
    __half2 (*s_qp)[33]     = (__half2(*)[33])(sm + QP_OFF);
    __half2 (*s_kp)[64][33] = (__half2(*)[64][33])(sm + KP_OFF);
    __half2* s_wv           = (__half2*)(sm + WV_OFF);

    const int t  = threadIdx.x;
    const int b  = blockIdx.y;
    const int q0 = blockIdx.x * 32;

    const __half2* qp = (const __half2*)(g_qp + ((size_t)b * Qv + q0) * Hv);
    const __half2* kp = (const __half2*)(g_kp + (size_t)b * Kv * Hv);

#pragma unroll
    for (int j = 0; j < 4; j++) {
        int i = t + j * 256;
        s_qp[i >> 5][i & 31] = qp[i];
    }
    if (t < 32) s_wv[t] = __floats2half2_rn(wv_g[2 * t], wv_g[2 * t + 1]);

#pragma unroll
    for (int j = 0; j < 8; j++) {
        int i = t + j * 256;
        s_kp[0][i >> 5][i & 31] = kp[i];
    }
    __syncthreads();

    const int tx = t & 31;
    const int ty = t >> 5;
    const int qb = ty << 2;

    for (int c = 0; c < 16; c++) {
        const int buf = c & 1;
        __half2 pre[8];
        if (c < 15) {
            const __half2* src = kp + (size_t)(c + 1) * 64 * 32;
#pragma unroll
            for (int j = 0; j < 8; j++) pre[j] = src[t + j * 256];
        }

        float facc[4][2] = {};
#pragma unroll
        for (int grp = 0; grp < 8; grp++) {
            __half2 acc2[4][2];
#pragma unroll
            for (int i = 0; i < 4; i++) {
                acc2[i][0] = __floats2half2_rn(0.f, 0.f);
                acc2[i][1] = __floats2half2_rn(0.f, 0.f);
            }
#pragma unroll
            for (int u = 0; u < 4; u++) {
                const int hp = grp * 4 + u;
                const __half2 w2  = s_wv[hp];
                const __half2 k20 = s_kp[buf][tx][hp];
                const __half2 k21 = s_kp[buf][tx + 32][hp];
#pragma unroll
                for (int i = 0; i < 4; i++) {
                    const __half2 q2 = s_qp[qb + i][hp];
                    __half2 xa = __hadd2(q2, k20);
                    __half2 xb = __hadd2(q2, k21);
                    uint32_t ta = tanh2(*(uint32_t*)&xa);
                    uint32_t tb = tanh2(*(uint32_t*)&xb);
                    acc2[i][0] = __hfma2(w2, *(__half2*)&ta, acc2[i][0]);
                    acc2[i][1] = __hfma2(w2, *(__half2*)&tb, acc2[i][1]);
                }
            }
#pragma unroll
            for (int i = 0; i < 4; i++) {
#pragma unroll
                for (int j = 0; j < 2; j++) {
                    float2 f = __half22float2(acc2[i][j]);
                    facc[i][j] += f.x + f.y;
                }
            }
        }

        const int kc = c * 64;
#pragma unroll
        for (int i = 0; i < 4; i++) {
            s_sc[qb + i][kc + tx]      = facc[i][0];
            s_sc[qb + i][kc + tx + 32] = facc[i][1];
        }

        if (c < 15) {
#pragma unroll
            for (int j = 0; j < 8; j++) {
                int i = t + j * 256;
                s_kp[buf ^ 1][i >> 5][i & 31] = pre[j];
            }
        }
        __syncthreads();
    }

    // ---- in-CTA softmax over each of 32 rows, emit bf16 hi/lo planes ----
    const int lane = t & 31;
    const int warp = t >> 5;
#pragma unroll
    for (int rr = 0; rr < 4; rr++) {
        const int r = warp * 4 + rr;
        float* row = s_sc[r];

        float m = -1e30f;
#pragma unroll
        for (int i = 0; i < 32; i++) m = fmaxf(m, row[lane + 32 * i]);
#pragma unroll
        for (int o = 16; o; o >>= 1) m = fmaxf(m, __shfl_xor_sync(~0u, m, o));

        float ssum = 0.f;
#pragma unroll
        for (int i = 0; i < 32; i++) {
            float e = __expf(row[lane + 32 * i] - m);
            row[lane + 32 * i] = e;
            ssum += e;
        }
#pragma unroll
        for (int o = 16; o; o >>= 1) ssum += __shfl_xor_sync(~0u, ssum, o);
        const float inv = 1.0f / ssum;

        const size_t rowbase = ((size_t)(b * 1024 + q0 + r)) * 1024;
#pragma unroll
        for (int i = 0; i < 32; i++) {
            float a = row[lane + 32 * i] * inv;
            __nv_bfloat16 h = __float2bfloat16(a);
            __nv_bfloat16 l = __float2bfloat16(a - __bfloat162float(h));
            g_ahi[rowbase + lane + 32 * i] = h;
            g_alo[rowbase + lane + 32 * i] = l;
        }
    }
}

// ---------------------------------------------------------------------------
// AV GEMM: out[b] = attn[b] @ values[b], bf16x3 HMMA (m16n8k16).
// CTA tile 64(M) x 128(N), K-step 32, 8 warps (warp tile 32x32), cp.async
// double buffer. grid (2, 16, 4), 256 threads, 55296 B dynamic smem.
// ---------------------------------------------------------------------------
#define AS_ROW 40
#define BS_ROW 136
#define A_PLANE (64 * AS_ROW)
#define B_PLANE (32 * BS_ROW)
#define SMEM_A_BYTES (2 * 2 * A_PLANE * 2)
#define SMEM_B_BYTES (2 * 2 * B_PLANE * 2)
#define SMEM_TOTAL_AV (SMEM_A_BYTES + SMEM_B_BYTES)

__global__ __launch_bounds__(256)
void av_mma_kernel(float* __restrict__ Out)
{
    extern __shared__ char dyn[];
    const uint32_t sA = s2u(dyn);
    const uint32_t sB = s2u(dyn + SMEM_A_BYTES);

    const int t = threadIdx.x, wid = t >> 5, lane = t & 31;
    const int wm = wid & 1;
    const int wn = wid >> 1;
    const int b = blockIdx.z;
    const int m0 = blockIdx.y * 64;
    const int n0 = blockIdx.x * 128;

    const __nv_bfloat16* Ah = g_ahi + ((size_t)b * 1024 + m0) * 1024;
    const __nv_bfloat16* Al = g_alo + ((size_t)b * 1024 + m0) * 1024;
    const __nv_bfloat16* Vh = g_vhi + (size_t)b * 1024 * 256 + n0;
    const __nv_bfloat16* Vl = g_vlo + (size_t)b * 1024 * 256 + n0;

    const int a_row = t >> 2, a_col = (t & 3) * 8;
    const int b_row = t >> 4, b_col = (t & 15) * 8;

    const int sub = lane >> 3, r8 = lane & 7;
    const uint32_t a_lane_off = (uint32_t)(((sub & 1) * 8 + r8) * (AS_ROW * 2) + (sub >> 1) * 16);
    const uint32_t b_lane_off = (uint32_t)(((sub & 1) * 8 + r8) * (BS_ROW * 2) + (sub >> 1) * 16);

    auto issue = [&](int step, int buf) {
        const size_t kb = (size_t)step * 32;
#pragma unroll
        for (int pl = 0; pl < 2; pl++) {
            const __nv_bfloat16* src = (pl ? Al : Ah) + (size_t)a_row * 1024 + kb + a_col;
            uint32_t d = sA + ((buf * 2 + pl) * A_PLANE + a_row * AS_ROW + a_col) * 2;
            cp16(d, src);
        }
#pragma unroll
        for (int pl = 0; pl < 2; pl++) {
#pragma unroll
            for (int rr = 0; rr < 2; rr++) {
                const int row = b_row + rr * 16;
                const __nv_bfloat16* src = (pl ? Vl : Vh) + (kb + row) * 256 + b_col;
                uint32_t d = sB + ((buf * 2 + pl) * B_PLANE + row * BS_ROW + b_col) * 2;
                cp16(d, src);
            }
        }
    };

    float acc[2][4][4] = {};

    issue(0, 0);
    cp_commit();

    for (int s = 0; s < 32; s++) {
        const int buf = s & 1;
        if (s < 31) { issue(s + 1, buf ^ 1); cp_commit(); cp_wait<1>(); }
        else        { cp_wait<0>(); }
        __syncthreads();

#pragma unroll
        for (int k0 = 0; k0 < 32; k0 += 16) {
            uint32_t Af[2][2][4];
#pragma unroll
            for (int pl = 0; pl < 2; pl++)
#pragma unroll
                for (int mt = 0; mt < 2; mt++) {
                    uint32_t addr = sA + ((buf * 2 + pl) * A_PLANE + (wm * 32 + mt * 16) * AS_ROW + k0) * 2 + a_lane_off;
                    ldsm4(Af[pl][mt], addr);
                }
            uint32_t Bf[2][4][2];
#pragma unroll
            for (int pl = 0; pl < 2; pl++)
#pragma unroll
                for (int ntp = 0; ntp < 2; ntp++) {
                    uint32_t rr[4];
                    uint32_t addr = sB + ((buf * 2 + pl) * B_PLANE + k0 * BS_ROW) * 2
                                  + (uint32_t)(wn * 64 + ntp * 32) + b_lane_off;
                    ldsm4t(rr, addr);
                    Bf[pl][ntp * 2][0] = rr[0]; Bf[pl][ntp * 2][1] = rr[1];
                    Bf[pl][ntp * 2 + 1][0] = rr[2]; Bf[pl][ntp * 2 + 1][1] = rr[3];
                }
#pragma unroll
            for (int mt = 0; mt < 2; mt++)
#pragma unroll
                for (int nt = 0; nt < 4; nt++) {
                    mma_bf16(acc[mt][nt], Af[0][mt], Bf[0][nt]);
                    mma_bf16(acc[mt][nt], Af[0][mt], Bf[1][nt]);
                    mma_bf16(acc[mt][nt], Af[1][mt], Bf[0][nt]);
                }
        }
        __syncthreads();
    }

    const int g  = lane >> 2;
    const int tq = lane & 3;
    float* Ob = Out + (size_t)b * 1024 * 256;
#pragma unroll
    for (int mt = 0; mt < 2; mt++)
#pragma unroll
        for (int nt = 0; nt < 4; nt++) {
            int row = m0 + wm * 32 + mt * 16 + g;
            int col = n0 + wn * 32 + nt * 8 + tq * 2;
            *(float2*)(Ob + (size_t)row * 256 + col)       = make_float2(acc[mt][nt][0], acc[mt][nt][1]);
            *(float2*)(Ob + (size_t)(row + 8) * 256 + col) = make_float2(acc[mt][nt][2], acc[mt][nt][3]);
        }
}

// ---------------------------------------------------------------------------
extern "C" void kernel_launch(void* const* d_in, const int* in_sizes, int n_in,
                              void* d_out, int out_size)
{
    (void)in_sizes; (void)n_in; (void)out_size;
    const float* queries = (const float*)d_in[0];
    const float* keys    = (const float*)d_in[1];
    const float* values  = (const float*)d_in[2];
    const float* W_q     = (const float*)d_in[3];
    const float* W_k     = (const float*)d_in[4];
    const float* w_v     = (const float*)d_in[5];
    float* out = (float*)d_out;

    cudaFuncSetAttribute(av_mma_kernel, cudaFuncAttributeMaxDynamicSharedMemorySize, SMEM_TOTAL_AV);
    cudaFuncSetAttribute(scores_softmax_kernel, cudaFuncAttributeMaxDynamicSharedMemorySize, SMEM_SC_TOTAL);

    // 1. fused projections (f16 out) + values bf16 split
    proj_vsplit_kernel<<<dim3(1, 256, 1), 256>>>(queries, keys, W_q, W_k, values);

    // 2. fused additive-tanh scores + softmax -> bf16 hi/lo attn planes
    scores_softmax_kernel<<<dim3(Qv / 32, Bv), 256, SMEM_SC_TOTAL>>>(w_v);

    // 3. out = attn @ values via bf16x3 HMMA (8 warps)
    av_mma_kernel<<<dim3(DVv / 128, Qv / 64, Bv), 256, SMEM_TOTAL_AV>>>(out);
}

// round 7
// speedup vs baseline: 1.0035x; 1.0035x over previous
#include <cuda_runtime.h>
#include <cuda_bf16.h>
#include <cuda_fp16.h>
#include <cstdint>
#include <cstddef>

// Problem dims
#define Bv  4
#define Qv  1024
#define Kv  1024
#define Dv  256
#define Hv  64
#define DVv 256

// Scratch (allocation-free rule: __device__ globals)
__device__ __align__(16) __half g_qp[Bv * Qv * Hv];                   // 512 KB (f16)
__device__ __align__(16) __half g_kp[Bv * Kv * Hv];                   // 512 KB
__device__ __align__(16) __nv_bfloat16 g_ahi[(size_t)Bv * Qv * Kv];   // 8 MB
__device__ __align__(16) __nv_bfloat16 g_alo[(size_t)Bv * Qv * Kv];   // 8 MB
__device__ __align__(16) __nv_bfloat16 g_vhi[Bv * Kv * DVv];          // 2 MB
__device__ __align__(16) __nv_bfloat16 g_vlo[Bv * Kv * DVv];          // 2 MB

__device__ __forceinline__ uint32_t tanh2(uint32_t x) {
    uint32_t y;
    asm("tanh.approx.f16x2 %0, %1;" : "=r"(y) : "r"(x));
    return y;
}

__device__ __forceinline__ uint32_t s2u(const void* p) {
    uint32_t a;
    asm("{ .reg .u64 t; cvta.to.shared.u64 t, %1; cvt.u32.u64 %0, t; }" : "=r"(a) : "l"(p));
    return a;
}

__device__ __forceinline__ void cp16(uint32_t dst, const void* src) {
    asm volatile("cp.async.cg.shared.global [%0], [%1], 16;" :: "r"(dst), "l"(src));
}
__device__ __forceinline__ void cp_commit() { asm volatile("cp.async.commit_group;"); }
template <int N> __device__ __forceinline__ void cp_wait() {
    asm volatile("cp.async.wait_group %0;" :: "n"(N));
}

__device__ __forceinline__ void ldsm4(uint32_t* r, uint32_t addr) {
    asm volatile("ldmatrix.sync.aligned.m8n8.x4.shared.b16 {%0,%1,%2,%3}, [%4];"
                 : "=r"(r[0]), "=r"(r[1]), "=r"(r[2]), "=r"(r[3]) : "r"(addr));
}
__device__ __forceinline__ void ldsm4t(uint32_t* r, uint32_t addr) {
    asm volatile("ldmatrix.sync.aligned.m8n8.x4.trans.shared.b16 {%0,%1,%2,%3}, [%4];"
                 : "=r"(r[0]), "=r"(r[1]), "=r"(r[2]), "=r"(r[3]) : "r"(addr));
}
__device__ __forceinline__ void mma_bf16(float* d, const uint32_t* a, const uint32_t* b) {
    asm volatile(
        "mma.sync.aligned.m16n8k16.row.col.f32.bf16.bf16.f32 "
        "{%0,%1,%2,%3},{%4,%5,%6,%7},{%8,%9},{%0,%1,%2,%3};"
        : "+f"(d[0]), "+f"(d[1]), "+f"(d[2]), "+f"(d[3])
        : "r"(a[0]), "r"(a[1]), "r"(a[2]), "r"(a[3]), "r"(b[0]), "r"(b[1]));
}

// ---------------------------------------------------------------------------
// Fused: projections (f16 output) + values bf16 hi/lo split.
// grid (1, 384): y<128 queries tiles (32 rows), y<256 keys tiles, y>=256 vsplit.
// GEMM: M-tile 32, N=64, BK=32, cp.async double-buffered, 2x4 microtile.
// ---------------------------------------------------------------------------
#define PJ_A_STG (32 * 32)        // floats per A stage
#define PJ_B_STG (32 * 64)        // floats per B stage
#define PJ_SMEM ((2 * (PJ_A_STG + PJ_B_STG)) * 4)   // 24576 B

__global__ __launch_bounds__(256)
void proj_vsplit_kernel(const float* __restrict__ Qg, const float* __restrict__ Kg,
                        const float* __restrict__ Wq, const float* __restrict__ Wk,
                        const float* __restrict__ Vg)
{
    if (blockIdx.y >= 256) {
        const int blk = blockIdx.y - 256;          // 0..127
#pragma unroll
        for (int it = 0; it < 8; it++) {
            size_t idx4 = (size_t)blk * 256 + threadIdx.x + (size_t)it * 32768;
            size_t i = idx4 * 4;
            float4 v = *(const float4*)(Vg + i);
            __nv_bfloat16 h0 = __float2bfloat16(v.x), h1 = __float2bfloat16(v.y);
            __nv_bfloat16 h2 = __float2bfloat16(v.z), h3 = __float2bfloat16(v.w);
            __nv_bfloat16 l0 = __float2bfloat16(v.x - __bfloat162float(h0));
            __nv_bfloat16 l1 = __float2bfloat16(v.y - __bfloat162float(h1));
            __nv_bfloat16 l2 = __float2bfloat16(v.z - __bfloat162float(h2));
            __nv_bfloat16 l3 = __float2bfloat16(v.w - __bfloat162float(h3));
            *(ushort4*)(g_vhi + i) = make_ushort4(*(uint16_t*)&h0, *(uint16_t*)&h1, *(uint16_t*)&h2, *(uint16_t*)&h3);
            *(ushort4*)(g_vlo + i) = make_ushort4(*(uint16_t*)&l0, *(uint16_t*)&l1, *(uint16_t*)&l2, *(uint16_t*)&l3);
        }
        return;
    }

    __shared__ float As[2][32][32];
    __shared__ float Bs[2][32][64];

    const bool isQ = blockIdx.y < 128;
    const int tile = blockIdx.y & 127;                  // 0..127
    const float* A = (isQ ? Qg : Kg) + (size_t)tile * 32 * 256;
    const float* B = isQ ? Wq : Wk;
    __half*      C = (isQ ? g_qp : g_kp) + (size_t)tile * 32 * 64;

    const int t = threadIdx.x;
    // A staging: 256 cp16 per stage (one per thread)
    const int a_row = t >> 3, a_c4 = (t & 7) * 4;
    // B staging: 512 cp16 per stage (two per thread)
    const int b_row0 = t >> 4,        b_c40 = (t & 15) * 4;      // idx t
    const int b_row1 = (t + 256) >> 4, b_c41 = (t & 15) * 4;     // idx t+256

    const uint32_t sA = s2u(&As[0][0][0]);
    const uint32_t sB = s2u(&Bs[0][0][0]);

    auto issue = [&](int s, int buf) {
        const int k0 = s * 32;
        cp16(sA + (buf * PJ_A_STG + a_row * 32 + a_c4) * 4, A + (size_t)a_row * 256 + k0 + a_c4);
        cp16(sB + (buf * PJ_B_STG + b_row0 * 64 + b_c40) * 4, B + (size_t)(k0 + b_row0) * 64 + b_c40);
        cp16(sB + (buf * PJ_B_STG + b_row1 * 64 + b_c41) * 4, B + (size_t)(k0 + b_row1) * 64 + b_c41);
    };

    const int trow = t >> 4;       // 0..15 -> rows trow*2, trow*2+1
    const int tcol = t & 15;       // 0..15 -> cols tcol*4..+3

    float acc[2][4] = {};

    issue(0, 0);
    cp_commit();

    for (int s = 0; s < 8; s++) {
        const int buf = s & 1;
        if (s < 7) { issue(s + 1, buf ^ 1); cp_commit(); cp_wait<1>(); }
        else       { cp_wait<0>(); }
        __syncthreads();

#pragma unroll
        for (int kk = 0; kk < 32; kk++) {
            float4 b4 = *(const float4*)&Bs[buf][kk][tcol << 2];
            float a0 = As[buf][trow * 2 + 0][kk];
            float a1 = As[buf][trow * 2 + 1][kk];
            acc[0][0] += a0 * b4.x; acc[0][1] += a0 * b4.y; acc[0][2] += a0 * b4.z; acc[0][3] += a0 * b4.w;
            acc[1][0] += a1 * b4.x; acc[1][1] += a1 * b4.y; acc[1][2] += a1 * b4.z; acc[1][3] += a1 * b4.w;
        }
        __syncthreads();
    }

#pragma unroll
    for (int i = 0; i < 2; i++) {
        __half2 h01 = __floats2half2_rn(acc[i][0], acc[i][1]);
        __half2 h23 = __floats2half2_rn(acc[i][2], acc[i][3]);
        uint2 pk = make_uint2(*(uint32_t*)&h01, *(uint32_t*)&h23);
        *(uint2*)(C + (size_t)(trow * 2 + i) * 64 + (tcol << 2)) = pk;
    }
}

// ---------------------------------------------------------------------------
// Fused scores + softmax: one CTA owns 16 q-rows x ALL K=1024.
// smem 84.7 KB -> 2 CTAs/SM; grid (64, 4) = 256 CTAs.
// ---------------------------------------------------------------------------
#define QT 16
#define SC_BYTES   (QT * 1024 * 4)          // 65536
#define QP_OFF     SC_BYTES
#define QP_BYTES   (QT * 33 * 8)            // 4224 (half2[16][33])
#define KP_OFF     (QP_OFF + QP_BYTES)
#define KP_BYTES   (2 * 64 * 33 * 4)        // 16896
#define WV_OFF     (KP_OFF + KP_BYTES)
#define SMEM_SC_TOTAL (WV_OFF + 128)        // 86784

__global__ __launch_bounds__(256)
void scores_softmax_kernel(const float* __restrict__ wv_g)
{
    extern __shared__ char sm[];
    float   (*s_sc)[1024]   = (float(*)[1024])sm;
    __half2 (*s_qp)[33]     = (__half2(*)[33])(sm + QP_OFF);
    __half2 (*s_kp)[64][33] = (__half2(*)[64][33])(sm + KP_OFF);
    __half2* s_wv           = (__half2*)(sm + WV_OFF);

    const int t  = threadIdx.x;
    const int b  = blockIdx.y;
    const int q0 = blockIdx.x * QT;

    const __half2* qp = (const __half2*)(g_qp + ((size_t)b * Qv + q0) * Hv);
    const __half2* kp = (const __half2*)(g_kp + (size_t)b * Kv * Hv);

    // load qp (16 x 32 half2) and wv
#pragma unroll
    for (int j = 0; j < 2; j++) {
        int i = t + j * 256;
        s_qp[i >> 5][i & 31] = qp[i];
    }
    if (t < 32) s_wv[t] = __floats2half2_rn(wv_g[2 * t], wv_g[2 * t + 1]);

#pragma unroll
    for (int j = 0; j < 8; j++) {
        int i = t + j * 256;
        s_kp[0][i >> 5][i & 31] = kp[i];
    }
    __syncthreads();

    const int tx = t & 31;
    const int ty = t >> 5;          // 0..7
    const int qb = ty << 1;         // 2 q-rows per thread

    for (int c = 0; c < 16; c++) {
        const int buf = c & 1;
        __half2 pre[8];
        if (c < 15) {
            const __half2* src = kp + (size_t)(c + 1) * 64 * 32;
#pragma unroll
            for (int j = 0; j < 8; j++) pre[j] = src[t + j * 256];
        }

        float facc[2][2] = {};
#pragma unroll
        for (int grp = 0; grp < 8; grp++) {
            __half2 acc2[2][2];
#pragma unroll
            for (int i = 0; i < 2; i++) {
                acc2[i][0] = __floats2half2_rn(0.f, 0.f);
                acc2[i][1] = __floats2half2_rn(0.f, 0.f);
            }
#pragma unroll
            for (int u = 0; u < 4; u++) {
                const int hp = grp * 4 + u;
                const __half2 w2  = s_wv[hp];
                const __half2 k20 = s_kp[buf][tx][hp];
                const __half2 k21 = s_kp[buf][tx + 32][hp];
#pragma unroll
                for (int i = 0; i < 2; i++) {
                    const __half2 q2 = s_qp[qb + i][hp];
                    __half2 xa = __hadd2(q2, k20);
                    __half2 xb = __hadd2(q2, k21);
                    uint32_t ta = tanh2(*(uint32_t*)&xa);
                    uint32_t tb = tanh2(*(uint32_t*)&xb);
                    acc2[i][0] = __hfma2(w2, *(__half2*)&ta, acc2[i][0]);
                    acc2[i][1] = __hfma2(w2, *(__half2*)&tb, acc2[i][1]);
                }
            }
#pragma unroll
            for (int i = 0; i < 2; i++) {
#pragma unroll
                for (int j = 0; j < 2; j++) {
                    float2 f = __half22float2(acc2[i][j]);
                    facc[i][j] += f.x + f.y;
                }
            }
        }

        const int kc = c * 64;
#pragma unroll
        for (int i = 0; i < 2; i++) {
            s_sc[qb + i][kc + tx]      = facc[i][0];
            s_sc[qb + i][kc + tx + 32] = facc[i][1];
        }

        if (c < 15) {
#pragma unroll
            for (int j = 0; j < 8; j++) {
                int i = t + j * 256;
                s_kp[buf ^ 1][i >> 5][i & 31] = pre[j];
            }
        }
        __syncthreads();
    }

    // ---- softmax over each of 16 rows (2 per warp), emit bf16 hi/lo ----
    const int lane = t & 31;
    const int warp = t >> 5;
#pragma unroll
    for (int rr = 0; rr < 2; rr++) {
        const int r = warp * 2 + rr;
        float* row = s_sc[r];

        float m = -1e30f;
#pragma unroll
        for (int i = 0; i < 32; i++) m = fmaxf(m, row[lane + 32 * i]);
#pragma unroll
        for (int o = 16; o; o >>= 1) m = fmaxf(m, __shfl_xor_sync(~0u, m, o));

        float ssum = 0.f;
#pragma unroll
        for (int i = 0; i < 32; i++) {
            float e = __expf(row[lane + 32 * i] - m);
            row[lane + 32 * i] = e;
            ssum += e;
        }
#pragma unroll
        for (int o = 16; o; o >>= 1) ssum += __shfl_xor_sync(~0u, ssum, o);
        const float inv = 1.0f / ssum;

        const size_t rowbase = ((size_t)(b * 1024 + q0 + r)) * 1024;
#pragma unroll
        for (int i = 0; i < 32; i++) {
            float a = row[lane + 32 * i] * inv;
            __nv_bfloat16 h = __float2bfloat16(a);
            __nv_bfloat16 l = __float2bfloat16(a - __bfloat162float(h));
            g_ahi[rowbase + lane + 32 * i] = h;
            g_alo[rowbase + lane + 32 * i] = l;
        }
    }
}

// ---------------------------------------------------------------------------
// AV GEMM: out[b] = attn[b] @ values[b], bf16x3 HMMA (m16n8k16).
// CTA tile 64(M) x 128(N), K-step 32, 8 warps (warp tile 32x32), cp.async DB.
// ---------------------------------------------------------------------------
#define AS_ROW 40
#define BS_ROW 136
#define A_PLANE (64 * AS_ROW)
#define B_PLANE (32 * BS_ROW)
#define SMEM_A_BYTES (2 * 2 * A_PLANE * 2)
#define SMEM_B_BYTES (2 * 2 * B_PLANE * 2)
#define SMEM_TOTAL_AV (SMEM_A_BYTES + SMEM_B_BYTES)

__global__ __launch_bounds__(256)
void av_mma_kernel(float* __restrict__ Out)
{
    extern __shared__ char dyn[];
    const uint32_t sA = s2u(dyn);
    const uint32_t sB = s2u(dyn + SMEM_A_BYTES);

    const int t = threadIdx.x, wid = t >> 5, lane = t & 31;
    const int wm = wid & 1;
    const int wn = wid >> 1;
    const int b = blockIdx.z;
    const int m0 = blockIdx.y * 64;
    const int n0 = blockIdx.x * 128;

    const __nv_bfloat16* Ah = g_ahi + ((size_t)b * 1024 + m0) * 1024;
    const __nv_bfloat16* Al = g_alo + ((size_t)b * 1024 + m0) * 1024;
    const __nv_bfloat16* Vh = g_vhi + (size_t)b * 1024 * 256 + n0;
    const __nv_bfloat16* Vl = g_vlo + (size_t)b * 1024 * 256 + n0;

    const int a_row = t >> 2, a_col = (t & 3) * 8;
    const int b_row = t >> 4, b_col = (t & 15) * 8;

    const int sub = lane >> 3, r8 = lane & 7;
    const uint32_t a_lane_off = (uint32_t)(((sub & 1) * 8 + r8) * (AS_ROW * 2) + (sub >> 1) * 16);
    const uint32_t b_lane_off = (uint32_t)(((sub & 1) * 8 + r8) * (BS_ROW * 2) + (sub >> 1) * 16);

    auto issue = [&](int step, int buf) {
        const size_t kb = (size_t)step * 32;
#pragma unroll
        for (int pl = 0; pl < 2; pl++) {
            const __nv_bfloat16* src = (pl ? Al : Ah) + (size_t)a_row * 1024 + kb + a_col;
            uint32_t d = sA + ((buf * 2 + pl) * A_PLANE + a_row * AS_ROW + a_col) * 2;
            cp16(d, src);
        }
#pragma unroll
        for (int pl = 0; pl < 2; pl++) {
#pragma unroll
            for (int rr = 0; rr < 2; rr++) {
                const int row = b_row + rr * 16;
                const __nv_bfloat16* src = (pl ? Vl : Vh) + (kb + row) * 256 + b_col;
                uint32_t d = sB + ((buf * 2 + pl) * B_PLANE + row * BS_ROW + b_col) * 2;
                cp16(d, src);
            }
        }
    };

    float acc[2][4][4] = {};

    issue(0, 0);
    cp_commit();

    for (int s = 0; s < 32; s++) {
        const int buf = s & 1;
        if (s < 31) { issue(s + 1, buf ^ 1); cp_commit(); cp_wait<1>(); }
        else        { cp_wait<0>(); }
        __syncthreads();

#pragma unroll
        for (int k0 = 0; k0 < 32; k0 += 16) {
            uint32_t Af[2][2][4];
#pragma unroll
            for (int pl = 0; pl < 2; pl++)
#pragma unroll
                for (int mt = 0; mt < 2; mt++) {
                    uint32_t addr = sA + ((buf * 2 + pl) * A_PLANE + (wm * 32 + mt * 16) * AS_ROW + k0) * 2 + a_lane_off;
                    ldsm4(Af[pl][mt], addr);
                }
            uint32_t Bf[2][4][2];
#pragma unroll
            for (int pl = 0; pl < 2; pl++)
#pragma unroll
                for (int ntp = 0; ntp < 2; ntp++) {
                    uint32_t rr[4];
                    uint32_t addr = sB + ((buf * 2 + pl) * B_PLANE + k0 * BS_ROW) * 2
                                  + (uint32_t)(wn * 64 + ntp * 32) + b_lane_off;
                    ldsm4t(rr, addr);
                    Bf[pl][ntp * 2][0] = rr[0]; Bf[pl][ntp * 2][1] = rr[1];
                    Bf[pl][ntp * 2 + 1][0] = rr[2]; Bf[pl][ntp * 2 + 1][1] = rr[3];
                }
#pragma unroll
            for (int mt = 0; mt < 2; mt++)
#pragma unroll
                for (int nt = 0; nt < 4; nt++) {
                    mma_bf16(acc[mt][nt], Af[0][mt], Bf[0][nt]);
                    mma_bf16(acc[mt][nt], Af[0][mt], Bf[1][nt]);
                    mma_bf16(acc[mt][nt], Af[1][mt], Bf[0][nt]);
                }
        }
        __syncthreads();
    }

    const int g  = lane >> 2;
    const int tq = lane & 3;
    float* Ob = Out + (size_t)b * 1024 * 256;
#pragma unroll
    for (int mt = 0; mt < 2; mt++)
#pragma unroll
        for (int nt = 0; nt < 4; nt++) {
            int row = m0 + wm * 32 + mt * 16 + g;
            int col = n0 + wn * 32 + nt * 8 + tq * 2;
            *(float2*)(Ob + (size_t)row * 256 + col)       = make_float2(acc[mt][nt][0], acc[mt][nt][1]);
            *(float2*)(Ob + (size_t)(row + 8) * 256 + col) = make_float2(acc[mt][nt][2], acc[mt][nt][3]);
        }
}

// ---------------------------------------------------------------------------
extern "C" void kernel_launch(void* const* d_in, const int* in_sizes, int n_in,
                              void* d_out, int out_size)
{
    (void)in_sizes; (void)n_in; (void)out_size;
    const float* queries = (const float*)d_in[0];
    const float* keys    = (const float*)d_in[1];
    const float* values  = (const float*)d_in[2];
    const float* W_q     = (const float*)d_in[3];
    const float* W_k     = (const float*)d_in[4];
    const float* w_v     = (const float*)d_in[5];
    float* out = (float*)d_out;

    cudaFuncSetAttribute(av_mma_kernel, cudaFuncAttributeMaxDynamicSharedMemorySize, SMEM_TOTAL_AV);
    cudaFuncSetAttribute(scores_softmax_kernel, cudaFuncAttributeMaxDynamicSharedMemorySize, SMEM_SC_TOTAL);

    // 1. fused projections (32-row tiles, cp.async DB) + values bf16 split
    proj_vsplit_kernel<<<dim3(1, 384, 1), 256>>>(queries, keys, W_q, W_k, values);

    // 2. fused additive-tanh scores + softmax (16-q tiles, 2 CTAs/SM)
    scores_softmax_kernel<<<dim3(Qv / QT, Bv), 256, SMEM_SC_TOTAL>>>(w_v);

    // 3. out = attn @ values via bf16x3 HMMA (8 warps)
    av_mma_kernel<<<dim3(DVv / 128, Qv / 64, Bv), 256, SMEM_TOTAL_AV>>>(out);
}

// round 8
// speedup vs baseline: 1.0175x; 1.0139x over previous
#include <cuda_runtime.h>
#include <cuda_bf16.h>
#include <cuda_fp16.h>
#include <cstdint>
#include <cstddef>

// Problem dims
#define Bv  4
#define Qv  1024
#define Kv  1024
#define Dv  256
#define Hv  64
#define DVv 256

// Scratch (allocation-free rule: __device__ globals)
__device__ __align__(16) __half g_qp[Bv * Qv * Hv];                   // 512 KB (f16)
__device__ __align__(16) __half g_kp[Bv * Kv * Hv];                   // 512 KB
__device__ __align__(16) __nv_bfloat16 g_ahi[(size_t)Bv * Qv * Kv];   // 8 MB
__device__ __align__(16) __nv_bfloat16 g_alo[(size_t)Bv * Qv * Kv];   // 8 MB
__device__ __align__(16) __nv_bfloat16 g_vhi[Bv * Kv * DVv];          // 2 MB
__device__ __align__(16) __nv_bfloat16 g_vlo[Bv * Kv * DVv];          // 2 MB

__device__ __forceinline__ uint32_t tanh2(uint32_t x) {
    uint32_t y;
    asm("tanh.approx.f16x2 %0, %1;" : "=r"(y) : "r"(x));
    return y;
}

__device__ __forceinline__ uint32_t s2u(const void* p) {
    uint32_t a;
    asm("{ .reg .u64 t; cvta.to.shared.u64 t, %1; cvt.u32.u64 %0, t; }" : "=r"(a) : "l"(p));
    return a;
}

__device__ __forceinline__ void cp16(uint32_t dst, const void* src) {
    asm volatile("cp.async.cg.shared.global [%0], [%1], 16;" :: "r"(dst), "l"(src));
}
__device__ __forceinline__ void cp_commit() { asm volatile("cp.async.commit_group;"); }
template <int N> __device__ __forceinline__ void cp_wait() {
    asm volatile("cp.async.wait_group %0;" :: "n"(N));
}

__device__ __forceinline__ void ldsm4(uint32_t* r, uint32_t addr) {
    asm volatile("ldmatrix.sync.aligned.m8n8.x4.shared.b16 {%0,%1,%2,%3}, [%4];"
                 : "=r"(r[0]), "=r"(r[1]), "=r"(r[2]), "=r"(r[3]) : "r"(addr));
}
__device__ __forceinline__ void ldsm4t(uint32_t* r, uint32_t addr) {
    asm volatile("ldmatrix.sync.aligned.m8n8.x4.trans.shared.b16 {%0,%1,%2,%3}, [%4];"
                 : "=r"(r[0]), "=r"(r[1]), "=r"(r[2]), "=r"(r[3]) : "r"(addr));
}
__device__ __forceinline__ void mma_bf16(float* d, const uint32_t* a, const uint32_t* b) {
    asm volatile(
        "mma.sync.aligned.m16n8k16.row.col.f32.bf16.bf16.f32 "
        "{%0,%1,%2,%3},{%4,%5,%6,%7},{%8,%9},{%0,%1,%2,%3};"
        : "+f"(d[0]), "+f"(d[1]), "+f"(d[2]), "+f"(d[3])
        : "r"(a[0]), "r"(a[1]), "r"(a[2]), "r"(a[3]), "r"(b[0]), "r"(b[1]));
}

// ---------------------------------------------------------------------------
// Fused: projections (f16 output) + values bf16 hi/lo split.
// grid (1, 384), 128 threads: y<128 Q tiles (32 rows), y<256 K tiles, else vsplit.
// GEMM: M=32, N=64, BK=32; A transposed in smem (conflict-free LDS.128),
// 4x4 microtile (16 FFMA / 2 LDS.128), A reg-prefetch + B cp.async, 1 sync/iter.
// ---------------------------------------------------------------------------
__global__ __launch_bounds__(128)
void proj_vsplit_kernel(const float* __restrict__ Qg, const float* __restrict__ Kg,
                        const float* __restrict__ Wq, const float* __restrict__ Wk,
                        const float* __restrict__ Vg)
{
    if (blockIdx.y >= 256) {
        const int blk = blockIdx.y - 256;          // 0..127
#pragma unroll
        for (int it = 0; it < 16; it++) {
            size_t idx4 = (size_t)blk * 128 + threadIdx.x + (size_t)it * 16384;
            size_t i = idx4 * 4;
            float4 v = *(const float4*)(Vg + i);
            __nv_bfloat16 h0 = __float2bfloat16(v.x), h1 = __float2bfloat16(v.y);
            __nv_bfloat16 h2 = __float2bfloat16(v.z), h3 = __float2bfloat16(v.w);
            __nv_bfloat16 l0 = __float2bfloat16(v.x - __bfloat162float(h0));
            __nv_bfloat16 l1 = __float2bfloat16(v.y - __bfloat162float(h1));
            __nv_bfloat16 l2 = __float2bfloat16(v.z - __bfloat162float(h2));
            __nv_bfloat16 l3 = __float2bfloat16(v.w - __bfloat162float(h3));
            *(ushort4*)(g_vhi + i) = make_ushort4(*(uint16_t*)&h0, *(uint16_t*)&h1, *(uint16_t*)&h2, *(uint16_t*)&h3);
            *(ushort4*)(g_vlo + i) = make_ushort4(*(uint16_t*)&l0, *(uint16_t*)&l1, *(uint16_t*)&l2, *(uint16_t*)&l3);
        }
        return;
    }

    __shared__ float AsT[2][32][36];   // [buf][kk][row], pad 36 -> 16B-aligned rows
    __shared__ float Bs[2][32][64];    // [buf][kk][col]

    const bool isQ = blockIdx.y < 128;
    const int tile = blockIdx.y & 127;                  // 0..127
    const float* A = (isQ ? Qg : Kg) + (size_t)tile * 32 * 256;
    const float* B = isQ ? Wq : Wk;
    __half*      C = (isQ ? g_qp : g_kp) + (size_t)tile * 32 * 64;

    const int t = threadIdx.x;
    // A: 2 float4 LDG per thread per stage (256 float4 = 32x32)
    const int ar0 = t >> 3,           ac0 = (t & 7) * 4;
    const int ar1 = (t + 128) >> 3,   ac1 = (t & 7) * 4;
    // B: 4 cp16 per thread per stage (512 float4 = 32x64)
    const uint32_t sB = s2u(&Bs[0][0][0]);

    auto ldgA = [&](int s, float4* r) {
        const int k0 = s * 32;
        r[0] = *(const float4*)(A + (size_t)ar0 * 256 + k0 + ac0);
        r[1] = *(const float4*)(A + (size_t)ar1 * 256 + k0 + ac1);
    };
    auto stsA = [&](int buf, const float4* r) {
        AsT[buf][ac0 + 0][ar0] = r[0].x; AsT[buf][ac0 + 1][ar0] = r[0].y;
        AsT[buf][ac0 + 2][ar0] = r[0].z; AsT[buf][ac0 + 3][ar0] = r[0].w;
        AsT[buf][ac1 + 0][ar1] = r[1].x; AsT[buf][ac1 + 1][ar1] = r[1].y;
        AsT[buf][ac1 + 2][ar1] = r[1].z; AsT[buf][ac1 + 3][ar1] = r[1].w;
    };
    auto cpB = [&](int s, int buf) {
        const int k0 = s * 32;
#pragma unroll
        for (int j = 0; j < 4; j++) {
            int idx = t + j * 128;
            int brow = idx >> 4, bc4 = (idx & 15) * 4;
            cp16(sB + (uint32_t)((buf * 2048 + brow * 64 + bc4) * 4),
                 B + (size_t)(k0 + brow) * 64 + bc4);
        }
    };

    const int r = t >> 4;     // 0..7 -> rows r*4..r*4+3
    const int c = t & 15;     // 0..15 -> cols c*4..c*4+3

    float acc[4][4] = {};
    float4 regA[2], regA2[2];

    ldgA(0, regA);
    cpB(0, 0);
    cp_commit();

    for (int s = 0; s < 8; s++) {
        const int buf = s & 1;
        stsA(buf, regA);
        if (s < 7) ldgA(s + 1, regA2);
        cp_wait<0>();            // B(s) is the only outstanding group
        __syncthreads();
        if (s < 7) { cpB(s + 1, buf ^ 1); cp_commit(); }   // overlaps compute(s)

#pragma unroll
        for (int kk = 0; kk < 32; kk++) {
            float4 a4 = *(const float4*)&AsT[buf][kk][r << 2];
            float4 b4 = *(const float4*)&Bs[buf][kk][c << 2];
            acc[0][0] += a4.x * b4.x; acc[0][1] += a4.x * b4.y; acc[0][2] += a4.x * b4.z; acc[0][3] += a4.x * b4.w;
            acc[1][0] += a4.y * b4.x; acc[1][1] += a4.y * b4.y; acc[1][2] += a4.y * b4.z; acc[1][3] += a4.y * b4.w;
            acc[2][0] += a4.z * b4.x; acc[2][1] += a4.z * b4.y; acc[2][2] += a4.z * b4.z; acc[2][3] += a4.z * b4.w;
            acc[3][0] += a4.w * b4.x; acc[3][1] += a4.w * b4.y; acc[3][2] += a4.w * b4.z; acc[3][3] += a4.w * b4.w;
        }
        regA[0] = regA2[0]; regA[1] = regA2[1];
    }

#pragma unroll
    for (int i = 0; i < 4; i++) {
        __half2 h01 = __floats2half2_rn(acc[i][0], acc[i][1]);
        __half2 h23 = __floats2half2_rn(acc[i][2], acc[i][3]);
        uint2 pk = make_uint2(*(uint32_t*)&h01, *(uint32_t*)&h23);
        *(uint2*)(C + (size_t)((r << 2) + i) * 64 + (c << 2)) = pk;
    }
}

// ---------------------------------------------------------------------------
// Fused scores + softmax (QT=32, the measured-better variant).
// One CTA owns 32 q-rows x all K=1024; grid (32, 4), 256 thr, 152320 B smem.
// ---------------------------------------------------------------------------
#define QT 32
#define SC_BYTES   (QT * 1024 * 4)          // 131072
#define QP_OFF     SC_BYTES
#define QP_BYTES   (QT * 33 * 8)            // 8448
#define KP_OFF     (QP_OFF + QP_BYTES)
#define KP_BYTES   (2 * 64 * 33 * 4)        // 16896
#define WV_OFF     (KP_OFF + KP_BYTES)
#define SMEM_SC_TOTAL (WV_OFF + 128)

__global__ __launch_bounds__(256)
void scores_softmax_kernel(const float* __restrict__ wv_g)
{
    extern __shared__ char sm[];
    float   (*s_sc)[1024]   = (float(*)[1024])sm;
    __half2 (*s_qp)[33]     = (__half2(*)[33])(sm + QP_OFF);
    __half2 (*s_kp)[64][33] = (__half2(*)[64][33])(sm + KP_OFF);
    __half2* s_wv           = (__half2*)(sm + WV_OFF);

    const int t  = threadIdx.x;
    const int b  = blockIdx.y;
    const int q0 = blockIdx.x * QT;

    const __half2* qp = (const __half2*)(g_qp + ((size_t)b * Qv + q0) * Hv);
    const __half2* kp = (const __half2*)(g_kp + (size_t)b * Kv * Hv);

#pragma unroll
    for (int j = 0; j < 4; j++) {
        int i = t + j * 256;
        s_qp[i >> 5][i & 31] = qp[i];
    }
    if (t < 32) s_wv[t] = __floats2half2_rn(wv_g[2 * t], wv_g[2 * t + 1]);

#pragma unroll
    for (int j = 0; j < 8; j++) {
        int i = t + j * 256;
        s_kp[0][i >> 5][i & 31] = kp[i];
    }
    __syncthreads();

    const int tx = t & 31;
    const int ty = t >> 5;
    const int qb = ty << 2;

    for (int c = 0; c < 16; c++) {
        const int buf = c & 1;
        __half2 pre[8];
        if (c < 15) {
            const __half2* src = kp + (size_t)(c + 1) * 64 * 32;
#pragma unroll
            for (int j = 0; j < 8; j++) pre[j] = src[t + j * 256];
        }

        float facc[4][2] = {};
#pragma unroll
        for (int grp = 0; grp < 8; grp++) {
            __half2 acc2[4][2];
#pragma unroll
            for (int i = 0; i < 4; i++) {
                acc2[i][0] = __floats2half2_rn(0.f, 0.f);
                acc2[i][1] = __floats2half2_rn(0.f, 0.f);
            }
#pragma unroll
            for (int u = 0; u < 4; u++) {
                const int hp = grp * 4 + u;
                const __half2 w2  = s_wv[hp];
                const __half2 k20 = s_kp[buf][tx][hp];
                const __half2 k21 = s_kp[buf][tx + 32][hp];
#pragma unroll
                for (int i = 0; i < 4; i++) {
                    const __half2 q2 = s_qp[qb + i][hp];
                    __half2 xa = __hadd2(q2, k20);
                    __half2 xb = __hadd2(q2, k21);
                    uint32_t ta = tanh2(*(uint32_t*)&xa);
                    uint32_t tb = tanh2(*(uint32_t*)&xb);
                    acc2[i][0] = __hfma2(w2, *(__half2*)&ta, acc2[i][0]);
                    acc2[i][1] = __hfma2(w2, *(__half2*)&tb, acc2[i][1]);
                }
            }
#pragma unroll
            for (int i = 0; i < 4; i++) {
#pragma unroll
                for (int j = 0; j < 2; j++) {
                    float2 f = __half22float2(acc2[i][j]);
                    facc[i][j] += f.x + f.y;
                }
            }
        }

        const int kc = c * 64;
#pragma unroll
        for (int i = 0; i < 4; i++) {
            s_sc[qb + i][kc + tx]      = facc[i][0];
            s_sc[qb + i][kc + tx + 32] = facc[i][1];
        }

        if (c < 15) {
#pragma unroll
            for (int j = 0; j < 8; j++) {
                int i = t + j * 256;
                s_kp[buf ^ 1][i >> 5][i & 31] = pre[j];
            }
        }
        __syncthreads();
    }

    // ---- softmax over each of 32 rows (4 per warp), emit bf16 hi/lo ----
    const int lane = t & 31;
    const int warp = t >> 5;
#pragma unroll
    for (int rr = 0; rr < 4; rr++) {
        const int r = warp * 4 + rr;
        float* row = s_sc[r];

        float m = -1e30f;
#pragma unroll
        for (int i = 0; i < 32; i++) m = fmaxf(m, row[lane + 32 * i]);
#pragma unroll
        for (int o = 16; o; o >>= 1) m = fmaxf(m, __shfl_xor_sync(~0u, m, o));

        float ssum = 0.f;
#pragma unroll
        for (int i = 0; i < 32; i++) {
            float e = __expf(row[lane + 32 * i] - m);
            row[lane + 32 * i] = e;
            ssum += e;
        }
#pragma unroll
        for (int o = 16; o; o >>= 1) ssum += __shfl_xor_sync(~0u, ssum, o);
        const float inv = 1.0f / ssum;

        const size_t rowbase = ((size_t)(b * 1024 + q0 + r)) * 1024;
#pragma unroll
        for (int i = 0; i < 32; i++) {
            float a = row[lane + 32 * i] * inv;
            __nv_bfloat16 h = __float2bfloat16(a);
            __nv_bfloat16 l = __float2bfloat16(a - __bfloat162float(h));
            g_ahi[rowbase + lane + 32 * i] = h;
            g_alo[rowbase + lane + 32 * i] = l;
        }
    }
}

// ---------------------------------------------------------------------------
// AV GEMM: out[b] = attn[b] @ values[b], bf16x3 HMMA (m16n8k16).
// CTA tile 64x128, K-step 32, 8 warps (32x32 each), 3-stage cp.async,
// single __syncthreads per iter, 2 stages always in flight.
// ---------------------------------------------------------------------------
#define AS_ROW 40
#define BS_ROW 136
#define A_PLANE (64 * AS_ROW)
#define B_PLANE (32 * BS_ROW)
#define NSTG 3
#define STG_A_BYTES (2 * A_PLANE * 2)      // both planes, one stage: 10240
#define STG_B_BYTES (2 * B_PLANE * 2)      // 17408
#define SMEM_A_BYTES (NSTG * STG_A_BYTES)  // 30720
#define SMEM_B_BYTES (NSTG * STG_B_BYTES)  // 52224
#define SMEM_TOTAL_AV (SMEM_A_BYTES + SMEM_B_BYTES)   // 82944

__global__ __launch_bounds__(256)
void av_mma_kernel(float* __restrict__ Out)
{
    extern __shared__ char dyn[];
    const uint32_t sA = s2u(dyn);
    const uint32_t sB = s2u(dyn + SMEM_A_BYTES);

    const int t = threadIdx.x, wid = t >> 5, lane = t & 31;
    const int wm = wid & 1;
    const int wn = wid >> 1;
    const int b = blockIdx.z;
    const int m0 = blockIdx.y * 64;
    const int n0 = blockIdx.x * 128;

    const __nv_bfloat16* Ah = g_ahi + ((size_t)b * 1024 + m0) * 1024;
    const __nv_bfloat16* Al = g_alo + ((size_t)b * 1024 + m0) * 1024;
    const __nv_bfloat16* Vh = g_vhi + (size_t)b * 1024 * 256 + n0;
    const __nv_bfloat16* Vl = g_vlo + (size_t)b * 1024 * 256 + n0;

    const int a_row = t >> 2, a_col = (t & 3) * 8;
    const int b_row = t >> 4, b_col = (t & 15) * 8;

    const int sub = lane >> 3, r8 = lane & 7;
    const uint32_t a_lane_off = (uint32_t)(((sub & 1) * 8 + r8) * (AS_ROW * 2) + (sub >> 1) * 16);
    const uint32_t b_lane_off = (uint32_t)(((sub & 1) * 8 + r8) * (BS_ROW * 2) + (sub >> 1) * 16);

    auto issue = [&](int step, int buf) {
        const size_t kb = (size_t)step * 32;
#pragma unroll
        for (int pl = 0; pl < 2; pl++) {
            const __nv_bfloat16* src = (pl ? Al : Ah) + (size_t)a_row * 1024 + kb + a_col;
            uint32_t d = sA + (uint32_t)(buf * STG_A_BYTES) + (uint32_t)((pl * A_PLANE + a_row * AS_ROW + a_col) * 2);
            cp16(d, src);
        }
#pragma unroll
        for (int pl = 0; pl < 2; pl++) {
#pragma unroll
            for (int rr = 0; rr < 2; rr++) {
                const int row = b_row + rr * 16;
                const __nv_bfloat16* src = (pl ? Vl : Vh) + (kb + row) * 256 + b_col;
                uint32_t d = sB + (uint32_t)(buf * STG_B_BYTES) + (uint32_t)((pl * B_PLANE + row * BS_ROW + b_col) * 2);
                cp16(d, src);
            }
        }
    };

    float acc[2][4][4] = {};

    issue(0, 0); cp_commit();
    issue(1, 1); cp_commit();

    int buf = 0;
    for (int s = 0; s < 32; s++) {
        if (s < 31) cp_wait<1>(); else cp_wait<0>();
        __syncthreads();
        if (s < 30) {
            int nb = buf + 2; if (nb >= NSTG) nb -= NSTG;
            issue(s + 2, nb);
            cp_commit();
        }

#pragma unroll
        for (int k0 = 0; k0 < 32; k0 += 16) {
            uint32_t Af[2][2][4];
#pragma unroll
            for (int pl = 0; pl < 2; pl++)
#pragma unroll
                for (int mt = 0; mt < 2; mt++) {
                    uint32_t addr = sA + (uint32_t)(buf * STG_A_BYTES)
                                  + (uint32_t)((pl * A_PLANE + (wm * 32 + mt * 16) * AS_ROW + k0) * 2) + a_lane_off;
                    ldsm4(Af[pl][mt], addr);
                }
            uint32_t Bf[2][4][2];
#pragma unroll
            for (int pl = 0; pl < 2; pl++)
#pragma unroll
                for (int ntp = 0; ntp < 2; ntp++) {
                    uint32_t rr[4];
                    uint32_t addr = sB + (uint32_t)(buf * STG_B_BYTES)
                                  + (uint32_t)((pl * B_PLANE + k0 * BS_ROW) * 2)
                                  + (uint32_t)(wn * 64 + ntp * 32) + b_lane_off;
                    ldsm4t(rr, addr);
                    Bf[pl][ntp * 2][0] = rr[0]; Bf[pl][ntp * 2][1] = rr[1];
                    Bf[pl][ntp * 2 + 1][0] = rr[2]; Bf[pl][ntp * 2 + 1][1] = rr[3];
                }
#pragma unroll
            for (int mt = 0; mt < 2; mt++)
#pragma unroll
                for (int nt = 0; nt < 4; nt++) {
                    mma_bf16(acc[mt][nt], Af[0][mt], Bf[0][nt]);
                    mma_bf16(acc[mt][nt], Af[0][mt], Bf[1][nt]);
                    mma_bf16(acc[mt][nt], Af[1][mt], Bf[0][nt]);
                }
        }
        buf++; if (buf >= NSTG) buf -= NSTG;
    }

    const int g  = lane >> 2;
    const int tq = lane & 3;
    float* Ob = Out + (size_t)b * 1024 * 256;
#pragma unroll
    for (int mt = 0; mt < 2; mt++)
#pragma unroll
        for (int nt = 0; nt < 4; nt++) {
            int row = m0 + wm * 32 + mt * 16 + g;
            int col = n0 + wn * 32 + nt * 8 + tq * 2;
            *(float2*)(Ob + (size_t)row * 256 + col)       = make_float2(acc[mt][nt][0], acc[mt][nt][1]);
            *(float2*)(Ob + (size_t)(row + 8) * 256 + col) = make_float2(acc[mt][nt][2], acc[mt][nt][3]);
        }
}

// ---------------------------------------------------------------------------
extern "C" void kernel_launch(void* const* d_in, const int* in_sizes, int n_in,
                              void* d_out, int out_size)
{
    (void)in_sizes; (void)n_in; (void)out_size;
    const float* queries = (const float*)d_in[0];
    const float* keys    = (const float*)d_in[1];
    const float* values  = (const float*)d_in[2];
    const float* W_q     = (const float*)d_in[3];
    const float* W_k     = (const float*)d_in[4];
    const float* w_v     = (const float*)d_in[5];
    float* out = (float*)d_out;

    cudaFuncSetAttribute(av_mma_kernel, cudaFuncAttributeMaxDynamicSharedMemorySize, SMEM_TOTAL_AV);
    cudaFuncSetAttribute(scores_softmax_kernel, cudaFuncAttributeMaxDynamicSharedMemorySize, SMEM_SC_TOTAL);

    // 1. fused projections (transposed-A 4x4 tiles) + values bf16 split
    proj_vsplit_kernel<<<dim3(1, 384, 1), 128>>>(queries, keys, W_q, W_k, values);

    // 2. fused additive-tanh scores + softmax (QT=32)
    scores_softmax_kernel<<<dim3(Qv / QT, Bv), 256, SMEM_SC_TOTAL>>>(w_v);

    // 3. out = attn @ values via bf16x3 HMMA (8 warps, 3-stage pipeline)
    av_mma_kernel<<<dim3(DVv / 128, Qv / 64, Bv), 256, SMEM_TOTAL_AV>>>(out);
}